// round 1
// baseline (speedup 1.0000x reference)
#include <cuda_runtime.h>
#include <math.h>

#define Bq 4
#define Lq 2048
#define Hq 8
#define Dq 64
#define NSLOT 12   // self + offsets 2^0 .. 2^10 (2^10 = 1024 <= 2047)

__global__ __launch_bounds__(256) void logsparse_attn_kernel(
    const float* __restrict__ Q,
    const float* __restrict__ K,
    const float* __restrict__ V,
    float* __restrict__ O)
{
    const int warp_global = (blockIdx.x * blockDim.x + threadIdx.x) >> 5;
    const int lane = threadIdx.x & 31;
    const int total = Bq * Lq * Hq;
    if (warp_global >= total) return;

    const int h = warp_global % Hq;
    const int l = (warp_global / Hq) % Lq;
    const int b = warp_global / (Hq * Lq);

    // row base (in float2 units: D/2 = 32 per row, one per lane)
    const size_t rowQ = ((size_t)(b * Lq + l) * Hq + h) * (Dq / 2);
    const float2* __restrict__ Q2 = (const float2*)Q;
    const float2* __restrict__ K2 = (const float2*)K;
    const float2* __restrict__ V2 = (const float2*)V;

    const float2 qv = Q2[rowQ + lane];

    // ---- gather K rows + dot products (fully unrolled; loads front-batched) ----
    float2 kv[NSLOT];
    int   jidx[NSLOT];
    bool  valid[NSLOT];
#pragma unroll
    for (int t = 0; t < NSLOT; t++) {
        int j; bool ok;
        if (t == 0) { j = l; ok = true; }
        else { int off = 1 << (t - 1); ok = (off <= l); j = l - (ok ? off : 0); }
        jidx[t] = j;
        valid[t] = ok;
        const size_t row = ((size_t)(b * Lq + j) * Hq + h) * (Dq / 2);
        kv[t] = K2[row + lane];   // safe: j clamped into range even when !ok
    }

    float score[NSLOT];
#pragma unroll
    for (int t = 0; t < NSLOT; t++) {
        float p = qv.x * kv[t].x + qv.y * kv[t].y;
#pragma unroll
        for (int m = 16; m > 0; m >>= 1)
            p += __shfl_xor_sync(0xffffffffu, p, m);
        score[t] = valid[t] ? (p * 0.125f) : -INFINITY;   // 1/sqrt(64)
    }

    // ---- softmax over <=12 entries (slot 0 = self always valid/finite) ----
    float mmax = score[0];
#pragma unroll
    for (int t = 1; t < NSLOT; t++) mmax = fmaxf(mmax, score[t]);

    float prob[NSLOT];
    float psum = 0.0f;
#pragma unroll
    for (int t = 0; t < NSLOT; t++) {
        float e = __expf(score[t] - mmax);   // -inf -> 0
        prob[t] = e;
        psum += e;
    }
    const float inv = 1.0f / psum;

    // ---- gather V rows, weighted accumulate ----
    float accx = 0.0f, accy = 0.0f;
#pragma unroll
    for (int t = 0; t < NSLOT; t++) {
        const size_t row = ((size_t)(b * Lq + jidx[t]) * Hq + h) * (Dq / 2);
        float2 vv = V2[row + lane];
        float p = prob[t];                    // 0 for invalid slots
        accx += p * vv.x;
        accy += p * vv.y;
    }

    float2 out;
    out.x = accx * inv;
    out.y = accy * inv;
    ((float2*)O)[rowQ + lane] = out;
}

extern "C" void kernel_launch(void* const* d_in, const int* in_sizes, int n_in,
                              void* d_out, int out_size)
{
    const float* Q = (const float*)d_in[0];
    const float* K = (const float*)d_in[1];
    const float* V = (const float*)d_in[2];
    float* O = (float*)d_out;

    const int total_warps = Bq * Lq * Hq;          // 65536
    const int threads = 256;                        // 8 warps per CTA
    const int blocks = (total_warps * 32 + threads - 1) / threads;  // 8192
    logsparse_attn_kernel<<<blocks, threads>>>(Q, K, V, O);
}